// round 6
// baseline (speedup 1.0000x reference)
#include <cuda_runtime.h>
#include <math.h>

#define BSZ 256        // batch B
#define NSEQ 4096      // K*B
#define H 64
#define G4 256         // 4*H
#define ZXD 320
#define LSTM_IN 322
#define TT 50

typedef unsigned long long ull;

// packed f32x2 helpers (ptxas never auto-fuses; PTX-only path)
#define FMA2(d, a, b, c) asm("fma.rn.f32x2 %0, %1, %2, %3;" : "=l"(d) : "l"(a), "l"(b), "l"(c))
#define PACKF2(d, x, y)  asm("mov.b64 %0, {%1, %2};" : "=l"(d) : "f"(x), "f"(y))
#define UNPACKF2(x, y, d) asm("mov.b64 {%0, %1}, %2;" : "=f"(x), "=f"(y) : "l"(d))

__device__ __forceinline__ float tanhg(float x) {
    float y;
    asm("tanh.approx.f32 %0, %1;" : "=f"(y) : "f"(x));
    return y;
}
__device__ __forceinline__ float sigg(float x) {
    return fmaf(0.5f, tanhg(0.5f * x), 0.5f);
}

// scratch
__device__ float g_G0[NSEQ * G4];   // interleaved: [n][u*4 + q]
__device__ float g_h0[NSEQ * H];
__device__ float g_c0[NSEQ * H];

// ---------------------------------------------------------------------------
// Phase 1:  [G0 | h0 | c0] = zx @ [Wih[:, :320] | Wh0 | Wc0]^T  (+ biases)
// ---------------------------------------------------------------------------
__global__ __launch_bounds__(256) void phase1_kernel(
    const float* __restrict__ x, const float* __restrict__ z,
    const float* __restrict__ Wih, const float* __restrict__ Wh0,
    const float* __restrict__ Wc0,
    const float* __restrict__ bih, const float* __restrict__ bhh,
    const float* __restrict__ bh0, const float* __restrict__ bc0)
{
    __shared__ float As[16][68];
    __shared__ float Ws[16][68];
    const int tid = threadIdx.x;
    const int n0 = blockIdx.x * 64;
    const int c0 = blockIdx.y * 64;
    const int tx = tid & 15, ty = tid >> 4;
    float acc[4][4] = {};

    for (int kt = 0; kt < ZXD; kt += 16) {
        #pragma unroll
        for (int i = 0; i < 4; i++) {
            int e = tid + i * 256;
            int kk = e & 15, rr = e >> 4;
            int n = n0 + rr, m = kt + kk;
            float v = (m < H) ? z[n * H + m]
                              : x[(n & (BSZ - 1)) * 256 + (m - H)];
            As[kk][rr] = v;
        }
        #pragma unroll
        for (int i = 0; i < 4; i++) {
            int e = tid + i * 256;
            int kk = e & 15, cc = e >> 4;
            int j = c0 + cc, m = kt + kk;
            float v;
            if (j < G4)          v = Wih[j * LSTM_IN + m];
            else if (j < G4 + H) v = Wh0[(j - G4) * ZXD + m];
            else                 v = Wc0[(j - G4 - H) * ZXD + m];
            Ws[kk][cc] = v;
        }
        __syncthreads();
        #pragma unroll
        for (int kk = 0; kk < 16; kk++) {
            float a[4], b[4];
            #pragma unroll
            for (int i = 0; i < 4; i++) a[i] = As[kk][ty * 4 + i];
            #pragma unroll
            for (int j = 0; j < 4; j++) b[j] = Ws[kk][tx * 4 + j];
            #pragma unroll
            for (int i = 0; i < 4; i++)
                #pragma unroll
                for (int j = 0; j < 4; j++)
                    acc[i][j] += a[i] * b[j];
        }
        __syncthreads();
    }

    #pragma unroll
    for (int i = 0; i < 4; i++) {
        int n = n0 + ty * 4 + i;
        #pragma unroll
        for (int j = 0; j < 4; j++) {
            int col = c0 + tx * 4 + j;
            float v = acc[i][j];
            if (col < G4) {
                int u = col & 63, q = col >> 6;
                g_G0[n * G4 + u * 4 + q] = v + bih[col] + bhh[col];
            }
            else if (col < G4 + H) g_h0[n * H + (col - G4)]     = v + bh0[col - G4];
            else                   g_c0[n * H + (col - G4 - H)] = v + bc0[col - G4 - H];
        }
    }
}

// ---------------------------------------------------------------------------
// Phase 2: warp-specialized pipeline.  128 blocks x 32 seqs x 512 threads.
// warps 0-7  (R):  gates GEMM + pointwise for step i        (critical path)
// warps 8-13 (Hd): heads GEMM for h_{i-1}
// warps 14-15(G):  GMM + LSE for h_{i-1}; decode prefetch
// One __syncthreads per step; H2 (h state) and DDE (decode) double-buffered.
// ---------------------------------------------------------------------------
#define PO_STRIDE 104

#define SM_WG   0                        // [64][256] packed Whh^T, 1KB rows
#define SM_WP   (SM_WG + 64 * 256)       // [64][96]  head weights^T, 384B rows
#define SM_WD   (SM_WP + 64 * 96)        // [2][128]  packed Wd pairs (ull)
#define SM_H2   (SM_WD + 512)            // [2][64][32] ull (h,h) pairs
#define SM_PO   (SM_H2 + 2 * 64 * 64)    // [32][104] head outputs
#define SM_DDX  (SM_PO + 32 * PO_STRIDE) // [2][32] ull (dx,dx)
#define SM_DDY  (SM_DDX + 128)           // [2][32] ull (dy,dy)
#define SM_TOT  (SM_DDY + 128)
#define SMEM_BYTES (SM_TOT * 4)

__global__ __launch_bounds__(512, 1) void phase2_kernel(
    const float* __restrict__ inp_seqs, const float* __restrict__ pred_seqs,
    const float* __restrict__ Whh, const float* __restrict__ Wih,
    const float* __restrict__ Wpi, const float* __restrict__ bpi,
    const float* __restrict__ Wmu, const float* __restrict__ bmu,
    const float* __restrict__ Wls, const float* __restrict__ bls,
    const float* __restrict__ Wcorr, const float* __restrict__ bcorr,
    float* __restrict__ out)
{
    extern __shared__ float sm[];
    char* smb = (char*)sm;
    const int tid  = threadIdx.x;
    const int lane = tid & 31;
    const int warp = tid >> 5;
    const int sg   = lane >> 2;       // 0..7 : seqs [4sg, 4sg+4)
    const int cg   = lane & 3;        // 0..3
    const int nb   = blockIdx.x * 32;

    // ---- stage weights ----
    // gates: Wg[k][col]; col = p*2+h2i, p = u*2+hh -> gate q = 2hh+h2i of unit u
    for (int e = tid; e < 64 * 256; e += 512) {
        int k = e >> 8, col = e & 255;
        int p = col >> 1, h2i = col & 1;
        int u = p >> 1, hh = p & 1;
        sm[SM_WG + k * 256 + col] = Whh[((hh * 2 + h2i) * 64 + u) * 64 + k];
    }
    // heads: Wp[k][j]
    for (int e = tid; e < 64 * 96; e += 512) {
        int j = e % 96, k = e / 96;
        float v;
        if (j < 16)      v = Wpi[j * 64 + k];
        else if (j < 48) v = Wmu[(j - 16) * 64 + k];
        else if (j < 80) v = Wls[(j - 48) * 64 + k];
        else             v = Wcorr[(j - 80) * 64 + k];
        sm[SM_WP + k * 96 + j] = v;
    }
    // Wd: [d][p] packed pairs
    for (int e = tid; e < 256; e += 512) {
        int d = e >> 7, p = e & 127;
        int u = p >> 1, hh = p & 1;
        sm[SM_WD + e * 2]     = Wih[((2 * hh) * 64 + u) * LSTM_IN + 320 + d];
        sm[SM_WD + e * 2 + 1] = Wih[((2 * hh + 1) * 64 + u) * LSTM_IN + 320 + d];
    }
    // DDE buf1 = tgt_present (used by gates at i=1)
    if (tid < 64) {
        int s = tid >> 1, d = tid & 1;
        int b = (nb + s) & (BSZ - 1);
        float v = inp_seqs[(b * 8 + 7) * 24 + 20 + d];
        int base = d ? SM_DDY : SM_DDX;
        sm[base + 64 + 2 * s]     = v;
        sm[base + 64 + 2 * s + 1] = v;
    }

    // ---- R state ----
    const int pbase = 16 * warp + 4 * cg;  // packed-col base (warp<8 only)
    const int u0 = pbase >> 1;
    ull G0p[4][4];
    float cr[4][2];
    if (warp < 8) {
        const ull* g0p = (const ull*)g_G0;
        #pragma unroll
        for (int j = 0; j < 4; j++) {
            int n = nb + 4 * sg + j;
            #pragma unroll
            for (int pp = 0; pp < 4; pp++)
                G0p[j][pp] = g0p[n * 128 + pbase + pp];
            cr[j][0] = g_c0[n * H + u0];
            cr[j][1] = g_c0[n * H + u0 + 1];
        }
        // h0 -> H2 buf0 as (h,h) pairs
        #pragma unroll
        for (int ui = 0; ui < 2; ui++) {
            int u = u0 + ui;
            float h0a = g_h0[(nb + 4 * sg + 0) * H + u];
            float h0b = g_h0[(nb + 4 * sg + 1) * H + u];
            float h0c = g_h0[(nb + 4 * sg + 2) * H + u];
            float h0d = g_h0[(nb + 4 * sg + 3) * H + u];
            ull q0, q1, q2, q3;
            PACKF2(q0, h0a, h0a); PACKF2(q1, h0b, h0b);
            PACKF2(q2, h0c, h0c); PACKF2(q3, h0d, h0d);
            ulonglong2 v0; v0.x = q0; v0.y = q1;
            ulonglong2 v1; v1.x = q2; v1.y = q3;
            char* hw = smb + SM_H2 * 4 + u * 256 + sg * 32;
            *(ulonglong2*)hw = v0;
            *(ulonglong2*)(hw + 16) = v1;
        }
    }

    // ---- Hd constants ----
    ull hb0 = 0, hb1 = 0;
    if (warp >= 8 && warp < 14) {
        int j0 = 16 * (warp - 8) + 4 * cg;
        float bv[4];
        #pragma unroll
        for (int jj = 0; jj < 4; jj++) {
            int j = j0 + jj;
            float v;
            if (j < 16)      v = bpi[j];
            else if (j < 48) v = bmu[j - 16];
            else if (j < 80) v = bls[j - 48];
            else             v = bcorr[j - 80];
            bv[jj] = v;
        }
        PACKF2(hb0, bv[0], bv[1]);
        PACKF2(hb1, bv[2], bv[3]);
    }

    // ---- G state ----
    const int sh = lane >> 4;     // 0/1
    const int gc = lane & 15;     // component
    float lacc[8] = {0.f, 0.f, 0.f, 0.f, 0.f, 0.f, 0.f, 0.f};

    __syncthreads();

    for (int i = 1; i <= TT + 1; i++) {
        const int rb = (i - 1) & 1;   // h buffer to read (h_{i-1})
        const int wbuf = i & 1;       // h buffer to write (h_i)
        const int db = i & 1;         // DDE buffer holding row i-2

        // ================= R: gates + pointwise (step i) =================
        if (warp < 8 && i <= TT) {
            ull acc[4][4];
            {
                const char* ddx = smb + SM_DDX * 4 + db * 256 + sg * 32;
                const char* ddy = smb + SM_DDY * 4 + db * 256 + sg * 32;
                ulonglong2 dxa = *(const ulonglong2*)ddx;
                ulonglong2 dxb = *(const ulonglong2*)(ddx + 16);
                ulonglong2 dya = *(const ulonglong2*)ddy;
                ulonglong2 dyb = *(const ulonglong2*)(ddy + 16);
                ull dx2[4] = {dxa.x, dxa.y, dxb.x, dxb.y};
                ull dy2[4] = {dya.x, dya.y, dyb.x, dyb.y};
                const char* wd = smb + SM_WD * 4 + pbase * 8;
                ulonglong2 wdxa = *(const ulonglong2*)wd;
                ulonglong2 wdxb = *(const ulonglong2*)(wd + 16);
                ulonglong2 wdya = *(const ulonglong2*)(wd + 1024);
                ulonglong2 wdyb = *(const ulonglong2*)(wd + 1024 + 16);
                ull wdx[4] = {wdxa.x, wdxa.y, wdxb.x, wdxb.y};
                ull wdy[4] = {wdya.x, wdya.y, wdyb.x, wdyb.y};
                #pragma unroll
                for (int j = 0; j < 4; j++)
                    #pragma unroll
                    for (int pp = 0; pp < 4; pp++) {
                        ull t0;
                        FMA2(t0, dx2[j], wdx[pp], G0p[j][pp]);
                        FMA2(acc[j][pp], dy2[j], wdy[pp], t0);
                    }
            }
            const char* h2p = smb + SM_H2 * 4 + rb * 16384 + sg * 32;
            const char* wgp = smb + SM_WG * 4 + pbase * 8;
            #pragma unroll 4
            for (int k = 0; k < 64; k++) {
                ulonglong2 ha  = *(const ulonglong2*)(h2p + k * 256);
                ulonglong2 hc  = *(const ulonglong2*)(h2p + k * 256 + 16);
                ulonglong2 wa  = *(const ulonglong2*)(wgp + k * 1024);
                ulonglong2 wb2 = *(const ulonglong2*)(wgp + k * 1024 + 16);
                FMA2(acc[0][0], ha.x, wa.x,  acc[0][0]);
                FMA2(acc[0][1], ha.x, wa.y,  acc[0][1]);
                FMA2(acc[0][2], ha.x, wb2.x, acc[0][2]);
                FMA2(acc[0][3], ha.x, wb2.y, acc[0][3]);
                FMA2(acc[1][0], ha.y, wa.x,  acc[1][0]);
                FMA2(acc[1][1], ha.y, wa.y,  acc[1][1]);
                FMA2(acc[1][2], ha.y, wb2.x, acc[1][2]);
                FMA2(acc[1][3], ha.y, wb2.y, acc[1][3]);
                FMA2(acc[2][0], hc.x, wa.x,  acc[2][0]);
                FMA2(acc[2][1], hc.x, wa.y,  acc[2][1]);
                FMA2(acc[2][2], hc.x, wb2.x, acc[2][2]);
                FMA2(acc[2][3], hc.x, wb2.y, acc[2][3]);
                FMA2(acc[3][0], hc.y, wa.x,  acc[3][0]);
                FMA2(acc[3][1], hc.y, wa.y,  acc[3][1]);
                FMA2(acc[3][2], hc.y, wb2.x, acc[3][2]);
                FMA2(acc[3][3], hc.y, wb2.y, acc[3][3]);
            }
            // pointwise + h store (duplicated pairs)
            float hh2[2][4];
            #pragma unroll
            for (int j = 0; j < 4; j++) {
                #pragma unroll
                for (int ui = 0; ui < 2; ui++) {
                    float gi, gf, gg, go;
                    UNPACKF2(gi, gf, acc[j][2 * ui]);
                    UNPACKF2(gg, go, acc[j][2 * ui + 1]);
                    float c = sigg(gf) * cr[j][ui] + sigg(gi) * tanhg(gg);
                    cr[j][ui] = c;
                    hh2[ui][j] = sigg(go) * tanhg(c);
                }
            }
            char* hw = smb + SM_H2 * 4 + wbuf * 16384 + sg * 32;
            #pragma unroll
            for (int ui = 0; ui < 2; ui++) {
                int u = u0 + ui;
                ull q0, q1, q2, q3;
                PACKF2(q0, hh2[ui][0], hh2[ui][0]);
                PACKF2(q1, hh2[ui][1], hh2[ui][1]);
                PACKF2(q2, hh2[ui][2], hh2[ui][2]);
                PACKF2(q3, hh2[ui][3], hh2[ui][3]);
                ulonglong2 v0; v0.x = q0; v0.y = q1;
                ulonglong2 v1; v1.x = q2; v1.y = q3;
                *(ulonglong2*)(hw + u * 256) = v0;
                *(ulonglong2*)(hw + u * 256 + 16) = v1;
            }
        }

        // ================= Hd: heads for h_{i-1} =================
        if (warp >= 8 && warp < 14 && i >= 2) {
            ull ph[4][2];
            #pragma unroll
            for (int j = 0; j < 4; j++) { ph[j][0] = hb0; ph[j][1] = hb1; }
            const char* h2p = smb + SM_H2 * 4 + rb * 16384 + sg * 32;
            const char* wpp = smb + SM_WP * 4 + (8 * (warp - 8) + 2 * cg) * 8;
            #pragma unroll 4
            for (int k = 0; k < 64; k++) {
                ulonglong2 ha = *(const ulonglong2*)(h2p + k * 256);
                ulonglong2 hc = *(const ulonglong2*)(h2p + k * 256 + 16);
                ulonglong2 w  = *(const ulonglong2*)(wpp + k * 384);
                FMA2(ph[0][0], ha.x, w.x, ph[0][0]);
                FMA2(ph[0][1], ha.x, w.y, ph[0][1]);
                FMA2(ph[1][0], ha.y, w.x, ph[1][0]);
                FMA2(ph[1][1], ha.y, w.y, ph[1][1]);
                FMA2(ph[2][0], hc.x, w.x, ph[2][0]);
                FMA2(ph[2][1], hc.x, w.y, ph[2][1]);
                FMA2(ph[3][0], hc.y, w.x, ph[3][0]);
                FMA2(ph[3][1], hc.y, w.y, ph[3][1]);
            }
            int j0 = 16 * (warp - 8) + 4 * cg;
            #pragma unroll
            for (int j = 0; j < 4; j++) {
                float a, b, c, d;
                UNPACKF2(a, b, ph[j][0]);
                UNPACKF2(c, d, ph[j][1]);
                *(float4*)(sm + SM_PO + (4 * sg + j) * PO_STRIDE + j0) =
                    make_float4(a, b, c, d);
            }
        }

        // ================= G: decode prefetch (row i-1) =================
        if (warp >= 14 && i <= TT) {
            int gt = (warp - 14) * 32 + lane;     // 0..63
            int s = gt >> 1, d = gt & 1;
            int b = (nb + s) & (BSZ - 1);
            float v = pred_seqs[(b * TT + (i - 1)) * 24 + 20 + d];
            int base = d ? SM_DDY : SM_DDX;
            int off = base + ((i + 1) & 1) * 64 + 2 * s;
            sm[off] = v;
            sm[off + 1] = v;
        }

        // ================= Hd+G sync, then GMM for h_{i-1} =================
        if (warp >= 8 && i >= 2) {
            asm volatile("bar.sync 1, 256;" ::: "memory");
            if (warp >= 14) {
                #pragma unroll
                for (int it = 0; it < 8; it++) {
                    int gs = (warp - 14) * 16 + it * 2 + sh;
                    float txv = sm[SM_DDX + db * 64 + 2 * gs];
                    float tyv = sm[SM_DDY + db * 64 + 2 * gs];
                    const float* pr = sm + SM_PO + gs * PO_STRIDE;
                    float pi  = pr[gc];
                    float2 mu  = *(const float2*)(pr + 16 + 2 * gc);
                    float2 lsv = *(const float2*)(pr + 48 + 2 * gc);
                    float corr = tanhg(pr[80 + gc]);
                    float ls0 = fminf(fmaxf(lsv.x, -10.f), 10.f);
                    float ls1 = fminf(fmaxf(lsv.y, -10.f), 10.f);
                    float dx = txv - mu.x, dy = tyv - mu.y;
                    float z0 = dx * __expf(-ls0);
                    float z1 = dy * __expf(-ls1);
                    float omr  = 1.f - corr * corr;
                    float quad = z0 * z0 + z1 * z1 - 2.f * corr * z0 * z1;
                    float cv = -1.8378770664093453f - (ls0 + ls1)
                               - 0.5f * __logf(omr) - 0.5f * __fdividef(quad, omr);
                    float a = pi + cv;
                    float b2 = pi;
                    float ma = a, mb = b2;
                    #pragma unroll
                    for (int xm = 1; xm < 16; xm <<= 1) {
                        ma = fmaxf(ma, __shfl_xor_sync(0xFFFFFFFFu, ma, xm));
                        mb = fmaxf(mb, __shfl_xor_sync(0xFFFFFFFFu, mb, xm));
                    }
                    float ea = __expf(a - ma);
                    float eb = __expf(b2 - mb);
                    #pragma unroll
                    for (int xm = 1; xm < 16; xm <<= 1) {
                        ea += __shfl_xor_sync(0xFFFFFFFFu, ea, xm);
                        eb += __shfl_xor_sync(0xFFFFFFFFu, eb, xm);
                    }
                    float lp = (ma + __logf(ea)) - (mb + __logf(eb));
                    lacc[it] += fminf(lp, 50.f);
                }
            }
        }

        __syncthreads();
    }

    if (warp >= 14 && (lane & 15) == 0) {
        #pragma unroll
        for (int it = 0; it < 8; it++) {
            int gs = (warp - 14) * 16 + it * 2 + sh;
            out[nb + gs] = lacc[it];
        }
    }
}

// ---------------------------------------------------------------------------
extern "C" void kernel_launch(void* const* d_in, const int* in_sizes, int n_in,
                              void* d_out, int out_size)
{
    const float* x      = (const float*)d_in[0];
    const float* z      = (const float*)d_in[1];
    const float* inps   = (const float*)d_in[2];
    const float* preds  = (const float*)d_in[3];
    const float* Wh0    = (const float*)d_in[4];
    const float* bh0    = (const float*)d_in[5];
    const float* Wc0    = (const float*)d_in[6];
    const float* bc0    = (const float*)d_in[7];
    const float* Wih    = (const float*)d_in[8];
    const float* Whh    = (const float*)d_in[9];
    const float* bih    = (const float*)d_in[10];
    const float* bhh    = (const float*)d_in[11];
    const float* Wpi    = (const float*)d_in[12];
    const float* bpi    = (const float*)d_in[13];
    const float* Wmu    = (const float*)d_in[14];
    const float* bmu    = (const float*)d_in[15];
    const float* Wls    = (const float*)d_in[16];
    const float* bls    = (const float*)d_in[17];
    const float* Wcorr  = (const float*)d_in[18];
    const float* bcorr  = (const float*)d_in[19];
    float* out = (float*)d_out;

    cudaFuncSetAttribute(phase2_kernel,
                         cudaFuncAttributeMaxDynamicSharedMemorySize, SMEM_BYTES);

    dim3 g1(NSEQ / 64, 384 / 64);
    phase1_kernel<<<g1, 256>>>(x, z, Wih, Wh0, Wc0, bih, bhh, bh0, bc0);

    phase2_kernel<<<NSEQ / 32, 512, SMEM_BYTES>>>(
        inps, preds, Whh, Wih,
        Wpi, bpi, Wmu, bmu, Wls, bls, Wcorr, bcorr, out);
}